// round 5
// baseline (speedup 1.0000x reference)
#include <cuda_runtime.h>
#include <cuda_bf16.h>
#include <cstdint>

// SANet attention via warp-level HMMA (mma.sync m16n8k16 bf16, base PTX).
// R5: 16 warps/CTA (key-split warp pairs), ldmatrix.x4 operand loads,
// cp.async double-buffered pipeline. Math identical to R3/R4.

namespace {
constexpr int HW  = 4096;
constexpr int BQ  = 128;
constexpr int BK  = 128;
constexpr int NKT = HW / BK;   // 32
constexpr int NT  = 512;       // 16 warps: (qblk 0..7) x (khalf 0..1)

constexpr int QK_STR = 72;     // 144B rows (9 x 16B chunks: ldmatrix conflict-free)
constexpr int V_STR  = 136;    // 272B rows (17 chunks)

constexpr int SK_ST  = 0;      // fp32 stage K/Q [64c][128], 32 KB
constexpr int SV_ST  = 32768;  // fp32 stage V, 32 KB
constexpr int BUF0   = 65536;
constexpr int KPLANE = BK * QK_STR * 2;          // 18432 B (hi); lo follows
constexpr int VPLANE = 64 * V_STR * 2;           // 17408 B
constexpr int OFF_VHI = 2 * KPLANE;
constexpr int BUF_SZ  = 2 * KPLANE + 2 * VPLANE; // 71680 B
constexpr int SMEM_BYTES = BUF0 + 2 * BUF_SZ;    // 208896 B
constexpr int KLO_E = KPLANE / 2;                // elems hi->lo
constexpr int VLO_E = VPLANE / 2;
}

__device__ __forceinline__ uint32_t smem_u32(const void* p) {
    uint32_t a;
    asm("{ .reg .u64 t; cvta.to.shared.u64 t, %1; cvt.u32.u64 %0, t; }"
        : "=r"(a) : "l"(p));
    return a;
}
__device__ __forceinline__ void cpa16(uint32_t s, const void* g) {
    asm volatile("cp.async.cg.shared.global [%0], [%1], 16;" :: "r"(s), "l"(g));
}
__device__ __forceinline__ void cpa_commit() {
    asm volatile("cp.async.commit_group;" ::: "memory");
}
__device__ __forceinline__ void cpa_wait0() {
    asm volatile("cp.async.wait_group 0;" ::: "memory");
}
__device__ __forceinline__ void ldsm4(uint32_t a, uint32_t* r) {
    asm volatile("ldmatrix.sync.aligned.m8n8.x4.shared.b16 {%0,%1,%2,%3}, [%4];"
                 : "=r"(r[0]), "=r"(r[1]), "=r"(r[2]), "=r"(r[3]) : "r"(a));
}
__device__ __forceinline__ void mma_bf16(float* d, const uint32_t* a,
                                         const uint32_t* b) {
    asm volatile(
        "mma.sync.aligned.m16n8k16.row.col.f32.bf16.bf16.f32 "
        "{%0,%1,%2,%3}, {%4,%5,%6,%7}, {%8,%9}, {%0,%1,%2,%3};"
        : "+f"(d[0]), "+f"(d[1]), "+f"(d[2]), "+f"(d[3])
        : "r"(a[0]), "r"(a[1]), "r"(a[2]), "r"(a[3]), "r"(b[0]), "r"(b[1]));
}
__device__ __forceinline__ void split_pack(float x, float y,
                                           uint32_t& hi, uint32_t& lo) {
    __nv_bfloat16 xh = __float2bfloat16_rn(x);
    __nv_bfloat16 yh = __float2bfloat16_rn(y);
    __nv_bfloat16 xl = __float2bfloat16_rn(x - __bfloat162float(xh));
    __nv_bfloat16 yl = __float2bfloat16_rn(y - __bfloat162float(yh));
    hi = (uint32_t)__bfloat16_as_ushort(xh) |
         ((uint32_t)__bfloat16_as_ushort(yh) << 16);
    lo = (uint32_t)__bfloat16_as_ushort(xl) |
         ((uint32_t)__bfloat16_as_ushort(yl) << 16);
}

// K/Q transpose-convert: stage [64c][128] fp32 -> [k][c] bf16 hi/lo planes
__device__ __forceinline__ void conv_K(const float* st, __nv_bfloat16* dhi, int tid) {
    const int k  = tid & 127;
    const int c0 = (tid >> 7) * 16;
    float f[16];
    #pragma unroll
    for (int j = 0; j < 16; ++j) f[j] = st[(c0 + j) * 128 + k];
    uint32_t h[8], l[8];
    #pragma unroll
    for (int j = 0; j < 8; ++j) split_pack(f[2 * j], f[2 * j + 1], h[j], l[j]);
    __nv_bfloat16* d = dhi + k * QK_STR + c0;
    *(uint4*)(d)              = make_uint4(h[0], h[1], h[2], h[3]);
    *(uint4*)(d + 8)          = make_uint4(h[4], h[5], h[6], h[7]);
    *(uint4*)(d + KLO_E)      = make_uint4(l[0], l[1], l[2], l[3]);
    *(uint4*)(d + KLO_E + 8)  = make_uint4(l[4], l[5], l[6], l[7]);
}
// V convert: stage [64c][128k] fp32 -> [c][k] bf16 hi/lo planes
__device__ __forceinline__ void conv_V(const float* st, __nv_bfloat16* dhi, int tid) {
    const int c  = tid >> 3;
    const int kq = (tid & 7) * 16;
    float f[16];
    #pragma unroll
    for (int j = 0; j < 4; ++j)
        *(float4*)(f + 4 * j) = *(const float4*)(st + c * 128 + kq + 4 * j);
    uint32_t h[8], l[8];
    #pragma unroll
    for (int j = 0; j < 8; ++j) split_pack(f[2 * j], f[2 * j + 1], h[j], l[j]);
    __nv_bfloat16* d = dhi + c * V_STR + kq;
    *(uint4*)(d)              = make_uint4(h[0], h[1], h[2], h[3]);
    *(uint4*)(d + 8)          = make_uint4(h[4], h[5], h[6], h[7]);
    *(uint4*)(d + VLO_E)      = make_uint4(l[0], l[1], l[2], l[3]);
    *(uint4*)(d + VLO_E + 8)  = make_uint4(l[4], l[5], l[6], l[7]);
}

__global__ __launch_bounds__(NT, 1)
void sanet_hmma(const float* __restrict__ content,
                const float* __restrict__ content_s,
                const float* __restrict__ style,
                float* __restrict__ out)
{
    extern __shared__ __align__(16) char smc[];
    const uint32_t sb = smem_u32(smc);
    float* stK = (float*)(smc + SK_ST);
    float* stV = (float*)(smc + SV_ST);

    const int tid   = threadIdx.x;
    const int wid   = tid >> 5;
    const int lane  = tid & 31;
    const int qblk  = wid & 7;
    const int khalf = wid >> 3;
    const int g     = lane >> 2;
    const int t     = lane & 3;
    const int b     = blockIdx.y;
    const int q0    = blockIdx.x * BQ;

    const float* Qg = content   + (size_t)b * 64 * HW;
    const float* Kg = content_s + (size_t)b * 64 * HW;
    const float* Vg = style     + (size_t)b * 64 * HW;
    float* outg     = out       + (size_t)b * 128 * HW;

    // per-lane ldmatrix offsets (bytes): 8 rows | col-half | hi/lo plane
    const uint32_t laneK = (uint32_t)(lane & 7) * 144u +
                           (uint32_t)((lane >> 3) & 1) * 16u +
                           (uint32_t)((lane >> 4) & 1) * (uint32_t)KPLANE;
    const uint32_t laneV = (uint32_t)(lane & 7) * 272u +
                           (uint32_t)((lane >> 3) & 1) * 16u +
                           (uint32_t)((lane >> 4) & 1) * (uint32_t)VPLANE;

    // ---- prologue: stage Q ----
    #pragma unroll
    for (int j = 0; j < 4; ++j) {
        const int idx = tid + 512 * j;
        const int c = idx >> 5, kc = idx & 31;
        cpa16(sb + SK_ST + c * 512 + kc * 16, Qg + (size_t)c * HW + q0 + kc * 4);
    }
    cpa_commit();
    cpa_wait0();
    __syncthreads();

    {   // content passthrough
        const int q  = tid & 127;
        const int c0 = (tid >> 7) * 16;
        #pragma unroll
        for (int j = 0; j < 16; ++j)
            outg[(size_t)(c0 + j) * HW + q0 + q] = stK[(c0 + j) * 128 + q];
    }
    conv_K(stK, (__nv_bfloat16*)(smc + BUF0), tid);
    __syncthreads();

    // ---- persistent Q A-fragments (scalar loads, once) ----
    uint32_t qa_hi[4][4], qa_lo[4][4];
    {
        const __nv_bfloat16* qrow =
            (const __nv_bfloat16*)(smc + BUF0) + (qblk * 16 + g) * QK_STR + 2 * t;
        #pragma unroll
        for (int s = 0; s < 4; ++s) {
            qa_hi[s][0] = *(const uint32_t*)(qrow + 16 * s);
            qa_hi[s][1] = *(const uint32_t*)(qrow + 8 * QK_STR + 16 * s);
            qa_hi[s][2] = *(const uint32_t*)(qrow + 16 * s + 8);
            qa_hi[s][3] = *(const uint32_t*)(qrow + 8 * QK_STR + 16 * s + 8);
            qa_lo[s][0] = *(const uint32_t*)(qrow + KLO_E + 16 * s);
            qa_lo[s][1] = *(const uint32_t*)(qrow + KLO_E + 8 * QK_STR + 16 * s);
            qa_lo[s][2] = *(const uint32_t*)(qrow + KLO_E + 16 * s + 8);
            qa_lo[s][3] = *(const uint32_t*)(qrow + KLO_E + 8 * QK_STR + 16 * s + 8);
        }
    }
    __syncthreads();

    // ---- prime tile 0 ----
    #pragma unroll
    for (int j = 0; j < 4; ++j) {
        const int idx = tid + 512 * j;
        const int c = idx >> 5, kc = idx & 31;
        cpa16(sb + SK_ST + c * 512 + kc * 16, Kg + (size_t)c * HW + kc * 4);
        cpa16(sb + SV_ST + c * 512 + kc * 16, Vg + (size_t)c * HW + kc * 4);
    }
    cpa_commit();
    cpa_wait0();
    __syncthreads();
    conv_K(stK, (__nv_bfloat16*)(smc + BUF0), tid);
    conv_V(stV, (__nv_bfloat16*)(smc + BUF0 + OFF_VHI), tid);
    __syncthreads();

    float oAcc[8][4];
    #pragma unroll
    for (int nt = 0; nt < 8; ++nt)
        #pragma unroll
        for (int i = 0; i < 4; ++i) oAcc[nt][i] = 0.0f;
    float l0sum = 0.0f, l1sum = 0.0f;

    for (int kt = 0; kt < NKT; ++kt) {
        if (kt + 1 < NKT) {
            const int kk1 = (kt + 1) * BK;
            #pragma unroll
            for (int j = 0; j < 4; ++j) {
                const int idx = tid + 512 * j;
                const int c = idx >> 5, kc = idx & 31;
                cpa16(sb + SK_ST + c * 512 + kc * 16,
                      Kg + (size_t)c * HW + kk1 + kc * 4);
                cpa16(sb + SV_ST + c * 512 + kc * 16,
                      Vg + (size_t)c * HW + kk1 + kc * 4);
            }
            cpa_commit();
        }

        const uint32_t bufb = sb + BUF0 + (uint32_t)(kt & 1) * BUF_SZ;
        const uint32_t kaddr = bufb + (uint32_t)khalf * 64u * 144u + laneK;
        const uint32_t vaddr = bufb + OFF_VHI + (uint32_t)khalf * 128u + laneV;

        // ---- GEMM1: S[16q x 64k] = Q.K^T ----
        float sAcc[8][4];
        #pragma unroll
        for (int nt = 0; nt < 8; ++nt)
            #pragma unroll
            for (int i = 0; i < 4; ++i) sAcc[nt][i] = 0.0f;

        #pragma unroll
        for (int s = 0; s < 4; ++s) {
            #pragma unroll
            for (int np = 0; np < 4; ++np) {
                uint32_t ra[4], rb[4];
                ldsm4(kaddr + (2 * np) * 1152u + s * 32u, ra);
                ldsm4(kaddr + (2 * np + 1) * 1152u + s * 32u, rb);
                mma_bf16(sAcc[2 * np],     qa_hi[s], ra);
                mma_bf16(sAcc[2 * np + 1], qa_hi[s], rb);
                mma_bf16(sAcc[2 * np],     qa_hi[s], ra + 2);
                mma_bf16(sAcc[2 * np + 1], qa_hi[s], rb + 2);
                mma_bf16(sAcc[2 * np],     qa_lo[s], ra);
                mma_bf16(sAcc[2 * np + 1], qa_lo[s], rb);
            }
        }

        // ---- softmax + in-place P fragment build ----
        float* flat = &sAcc[0][0];
        float r0 = 0.0f, r1 = 0.0f;
        #pragma unroll
        for (int s = 0; s < 4; ++s) {
            float p[8];
            #pragma unroll
            for (int i = 0; i < 8; ++i) p[i] = __expf(flat[8 * s + i]);
            r0 += (p[0] + p[1]) + (p[4] + p[5]);
            r1 += (p[2] + p[3]) + (p[6] + p[7]);
            uint32_t h01, l01, h23, l23, h45, l45, h67, l67;
            split_pack(p[0], p[1], h01, l01);
            split_pack(p[2], p[3], h23, l23);
            split_pack(p[4], p[5], h45, l45);
            split_pack(p[6], p[7], h67, l67);
            flat[8 * s + 0] = __uint_as_float(h01);
            flat[8 * s + 1] = __uint_as_float(h23);
            flat[8 * s + 2] = __uint_as_float(h45);
            flat[8 * s + 3] = __uint_as_float(h67);
            flat[8 * s + 4] = __uint_as_float(l01);
            flat[8 * s + 5] = __uint_as_float(l23);
            flat[8 * s + 6] = __uint_as_float(l45);
            flat[8 * s + 7] = __uint_as_float(l67);
        }
        r0 += __shfl_xor_sync(0xffffffffu, r0, 1);
        r0 += __shfl_xor_sync(0xffffffffu, r0, 2);
        r1 += __shfl_xor_sync(0xffffffffu, r1, 1);
        r1 += __shfl_xor_sync(0xffffffffu, r1, 2);
        l0sum += r0;
        l1sum += r1;

        // ---- GEMM2: O[16q x 64c] += P.V^T (partial over this key half) ----
        #pragma unroll
        for (int s = 0; s < 4; ++s) {
            uint32_t ah[4], al[4];
            #pragma unroll
            for (int i = 0; i < 4; ++i) {
                ah[i] = __float_as_uint(flat[8 * s + i]);
                al[i] = __float_as_uint(flat[8 * s + 4 + i]);
            }
            #pragma unroll
            for (int np = 0; np < 4; ++np) {
                uint32_t ra[4], rb[4];
                ldsm4(vaddr + (2 * np) * 2176u + s * 32u, ra);
                ldsm4(vaddr + (2 * np + 1) * 2176u + s * 32u, rb);
                mma_bf16(oAcc[2 * np],     ah, ra);
                mma_bf16(oAcc[2 * np + 1], ah, rb);
                mma_bf16(oAcc[2 * np],     ah, ra + 2);
                mma_bf16(oAcc[2 * np + 1], ah, rb + 2);
                mma_bf16(oAcc[2 * np],     al, ra);
                mma_bf16(oAcc[2 * np + 1], al, rb);
            }
        }

        // ---- convert staged tile kt+1 into the other buffer ----
        if (kt + 1 < NKT) {
            cpa_wait0();
            __syncthreads();
            char* dst = smc + BUF0 + ((kt + 1) & 1) * BUF_SZ;
            conv_K(stK, (__nv_bfloat16*)(dst), tid);
            conv_V(stV, (__nv_bfloat16*)(dst + OFF_VHI), tid);
        }
        __syncthreads();
    }

    // ---- epilogue: pair-reduce partial O and l via stage SMEM, store ----
    __syncthreads();
    float* redO = (float*)smc;             // 8 warps * 32 lanes * 32 floats = 32KB
    float* redL = (float*)(smc + 32768);   // 8 * 32 * 2 floats
    if (khalf == 1) {
        float* dst = redO + (qblk * 32 + lane) * 32;
        #pragma unroll
        for (int nt = 0; nt < 8; ++nt)
            #pragma unroll
            for (int i = 0; i < 4; ++i) dst[nt * 4 + i] = oAcc[nt][i];
        redL[(qblk * 32 + lane) * 2 + 0] = l0sum;
        redL[(qblk * 32 + lane) * 2 + 1] = l1sum;
    }
    __syncthreads();
    if (khalf == 0) {
        const float* src = redO + (qblk * 32 + lane) * 32;
        const float L0 = l0sum + redL[(qblk * 32 + lane) * 2 + 0];
        const float L1 = l1sum + redL[(qblk * 32 + lane) * 2 + 1];
        const float inv0 = 1.0f / L0;
        const float inv1 = 1.0f / L1;
        const int qa = q0 + qblk * 16 + g;
        const int qb = qa + 8;
        #pragma unroll
        for (int nt = 0; nt < 8; ++nt) {
            const int c = nt * 8 + 2 * t;
            outg[(size_t)(64 + c) * HW + qa] = (oAcc[nt][0] + src[nt * 4 + 0]) * inv0;
            outg[(size_t)(65 + c) * HW + qa] = (oAcc[nt][1] + src[nt * 4 + 1]) * inv0;
            outg[(size_t)(64 + c) * HW + qb] = (oAcc[nt][2] + src[nt * 4 + 2]) * inv1;
            outg[(size_t)(65 + c) * HW + qb] = (oAcc[nt][3] + src[nt * 4 + 3]) * inv1;
        }
    }
}

extern "C" void kernel_launch(void* const* d_in, const int* in_sizes, int n_in,
                              void* d_out, int out_size)
{
    const float* content   = (const float*)d_in[0];
    const float* content_s = (const float*)d_in[1];
    const float* style     = (const float*)d_in[2];
    float* out = (float*)d_out;

    cudaFuncSetAttribute(sanet_hmma, cudaFuncAttributeMaxDynamicSharedMemorySize,
                         SMEM_BYTES);
    dim3 grid(HW / BQ, 4);   // 128 CTAs
    sanet_hmma<<<grid, NT, SMEM_BYTES>>>(content, content_s, style, out);
}

// round 6
// speedup vs baseline: 1.0011x; 1.0011x over previous
#include <cuda_runtime.h>
#include <cuda_bf16.h>
#include <cstdint>

// SANet attention via warp-level HMMA (mma.sync m16n8k16 bf16, base PTX).
// R5: 16 warps/CTA (key-split warp pairs), ldmatrix.x4 operand loads,
// cp.async double-buffered pipeline. Math identical to R3/R4.

namespace {
constexpr int HW  = 4096;
constexpr int BQ  = 128;
constexpr int BK  = 128;
constexpr int NKT = HW / BK;   // 32
constexpr int NT  = 512;       // 16 warps: (qblk 0..7) x (khalf 0..1)

constexpr int QK_STR = 72;     // 144B rows (9 x 16B chunks: ldmatrix conflict-free)
constexpr int V_STR  = 136;    // 272B rows (17 chunks)

constexpr int SK_ST  = 0;      // fp32 stage K/Q [64c][128], 32 KB
constexpr int SV_ST  = 32768;  // fp32 stage V, 32 KB
constexpr int BUF0   = 65536;
constexpr int KPLANE = BK * QK_STR * 2;          // 18432 B (hi); lo follows
constexpr int VPLANE = 64 * V_STR * 2;           // 17408 B
constexpr int OFF_VHI = 2 * KPLANE;
constexpr int BUF_SZ  = 2 * KPLANE + 2 * VPLANE; // 71680 B
constexpr int SMEM_BYTES = BUF0 + 2 * BUF_SZ;    // 208896 B
constexpr int KLO_E = KPLANE / 2;                // elems hi->lo
constexpr int VLO_E = VPLANE / 2;
}

__device__ __forceinline__ uint32_t smem_u32(const void* p) {
    uint32_t a;
    asm("{ .reg .u64 t; cvta.to.shared.u64 t, %1; cvt.u32.u64 %0, t; }"
        : "=r"(a) : "l"(p));
    return a;
}
__device__ __forceinline__ void cpa16(uint32_t s, const void* g) {
    asm volatile("cp.async.cg.shared.global [%0], [%1], 16;" :: "r"(s), "l"(g));
}
__device__ __forceinline__ void cpa_commit() {
    asm volatile("cp.async.commit_group;" ::: "memory");
}
__device__ __forceinline__ void cpa_wait0() {
    asm volatile("cp.async.wait_group 0;" ::: "memory");
}
__device__ __forceinline__ void ldsm4(uint32_t a, uint32_t* r) {
    asm volatile("ldmatrix.sync.aligned.m8n8.x4.shared.b16 {%0,%1,%2,%3}, [%4];"
                 : "=r"(r[0]), "=r"(r[1]), "=r"(r[2]), "=r"(r[3]) : "r"(a));
}
__device__ __forceinline__ void mma_bf16(float* d, const uint32_t* a,
                                         const uint32_t* b) {
    asm volatile(
        "mma.sync.aligned.m16n8k16.row.col.f32.bf16.bf16.f32 "
        "{%0,%1,%2,%3}, {%4,%5,%6,%7}, {%8,%9}, {%0,%1,%2,%3};"
        : "+f"(d[0]), "+f"(d[1]), "+f"(d[2]), "+f"(d[3])
        : "r"(a[0]), "r"(a[1]), "r"(a[2]), "r"(a[3]), "r"(b[0]), "r"(b[1]));
}
__device__ __forceinline__ void split_pack(float x, float y,
                                           uint32_t& hi, uint32_t& lo) {
    __nv_bfloat16 xh = __float2bfloat16_rn(x);
    __nv_bfloat16 yh = __float2bfloat16_rn(y);
    __nv_bfloat16 xl = __float2bfloat16_rn(x - __bfloat162float(xh));
    __nv_bfloat16 yl = __float2bfloat16_rn(y - __bfloat162float(yh));
    hi = (uint32_t)__bfloat16_as_ushort(xh) |
         ((uint32_t)__bfloat16_as_ushort(yh) << 16);
    lo = (uint32_t)__bfloat16_as_ushort(xl) |
         ((uint32_t)__bfloat16_as_ushort(yl) << 16);
}

// K/Q transpose-convert: stage [64c][128] fp32 -> [k][c] bf16 hi/lo planes
__device__ __forceinline__ void conv_K(const float* st, __nv_bfloat16* dhi, int tid) {
    const int k  = tid & 127;
    const int c0 = (tid >> 7) * 16;
    float f[16];
    #pragma unroll
    for (int j = 0; j < 16; ++j) f[j] = st[(c0 + j) * 128 + k];
    uint32_t h[8], l[8];
    #pragma unroll
    for (int j = 0; j < 8; ++j) split_pack(f[2 * j], f[2 * j + 1], h[j], l[j]);
    __nv_bfloat16* d = dhi + k * QK_STR + c0;
    *(uint4*)(d)              = make_uint4(h[0], h[1], h[2], h[3]);
    *(uint4*)(d + 8)          = make_uint4(h[4], h[5], h[6], h[7]);
    *(uint4*)(d + KLO_E)      = make_uint4(l[0], l[1], l[2], l[3]);
    *(uint4*)(d + KLO_E + 8)  = make_uint4(l[4], l[5], l[6], l[7]);
}
// V convert: stage [64c][128k] fp32 -> [c][k] bf16 hi/lo planes
__device__ __forceinline__ void conv_V(const float* st, __nv_bfloat16* dhi, int tid) {
    const int c  = tid >> 3;
    const int kq = (tid & 7) * 16;
    float f[16];
    #pragma unroll
    for (int j = 0; j < 4; ++j)
        *(float4*)(f + 4 * j) = *(const float4*)(st + c * 128 + kq + 4 * j);
    uint32_t h[8], l[8];
    #pragma unroll
    for (int j = 0; j < 8; ++j) split_pack(f[2 * j], f[2 * j + 1], h[j], l[j]);
    __nv_bfloat16* d = dhi + c * V_STR + kq;
    *(uint4*)(d)              = make_uint4(h[0], h[1], h[2], h[3]);
    *(uint4*)(d + 8)          = make_uint4(h[4], h[5], h[6], h[7]);
    *(uint4*)(d + VLO_E)      = make_uint4(l[0], l[1], l[2], l[3]);
    *(uint4*)(d + VLO_E + 8)  = make_uint4(l[4], l[5], l[6], l[7]);
}

__global__ __launch_bounds__(NT, 1)
void sanet_hmma(const float* __restrict__ content,
                const float* __restrict__ content_s,
                const float* __restrict__ style,
                float* __restrict__ out)
{
    extern __shared__ __align__(16) char smc[];
    const uint32_t sb = smem_u32(smc);
    float* stK = (float*)(smc + SK_ST);
    float* stV = (float*)(smc + SV_ST);

    const int tid   = threadIdx.x;
    const int wid   = tid >> 5;
    const int lane  = tid & 31;
    const int qblk  = wid & 7;
    const int khalf = wid >> 3;
    const int g     = lane >> 2;
    const int t     = lane & 3;
    const int b     = blockIdx.y;
    const int q0    = blockIdx.x * BQ;

    const float* Qg = content   + (size_t)b * 64 * HW;
    const float* Kg = content_s + (size_t)b * 64 * HW;
    const float* Vg = style     + (size_t)b * 64 * HW;
    float* outg     = out       + (size_t)b * 128 * HW;

    // per-lane ldmatrix offsets (bytes): 8 rows | col-half | hi/lo plane
    const uint32_t laneK = (uint32_t)(lane & 7) * 144u +
                           (uint32_t)((lane >> 3) & 1) * 16u +
                           (uint32_t)((lane >> 4) & 1) * (uint32_t)KPLANE;
    const uint32_t laneV = (uint32_t)(lane & 7) * 272u +
                           (uint32_t)((lane >> 3) & 1) * 16u +
                           (uint32_t)((lane >> 4) & 1) * (uint32_t)VPLANE;

    // ---- prologue: stage Q ----
    #pragma unroll
    for (int j = 0; j < 4; ++j) {
        const int idx = tid + 512 * j;
        const int c = idx >> 5, kc = idx & 31;
        cpa16(sb + SK_ST + c * 512 + kc * 16, Qg + (size_t)c * HW + q0 + kc * 4);
    }
    cpa_commit();
    cpa_wait0();
    __syncthreads();

    {   // content passthrough
        const int q  = tid & 127;
        const int c0 = (tid >> 7) * 16;
        #pragma unroll
        for (int j = 0; j < 16; ++j)
            outg[(size_t)(c0 + j) * HW + q0 + q] = stK[(c0 + j) * 128 + q];
    }
    conv_K(stK, (__nv_bfloat16*)(smc + BUF0), tid);
    __syncthreads();

    // ---- persistent Q A-fragments (scalar loads, once) ----
    uint32_t qa_hi[4][4], qa_lo[4][4];
    {
        const __nv_bfloat16* qrow =
            (const __nv_bfloat16*)(smc + BUF0) + (qblk * 16 + g) * QK_STR + 2 * t;
        #pragma unroll
        for (int s = 0; s < 4; ++s) {
            qa_hi[s][0] = *(const uint32_t*)(qrow + 16 * s);
            qa_hi[s][1] = *(const uint32_t*)(qrow + 8 * QK_STR + 16 * s);
            qa_hi[s][2] = *(const uint32_t*)(qrow + 16 * s + 8);
            qa_hi[s][3] = *(const uint32_t*)(qrow + 8 * QK_STR + 16 * s + 8);
            qa_lo[s][0] = *(const uint32_t*)(qrow + KLO_E + 16 * s);
            qa_lo[s][1] = *(const uint32_t*)(qrow + KLO_E + 8 * QK_STR + 16 * s);
            qa_lo[s][2] = *(const uint32_t*)(qrow + KLO_E + 16 * s + 8);
            qa_lo[s][3] = *(const uint32_t*)(qrow + KLO_E + 8 * QK_STR + 16 * s + 8);
        }
    }
    __syncthreads();

    // ---- prime tile 0 ----
    #pragma unroll
    for (int j = 0; j < 4; ++j) {
        const int idx = tid + 512 * j;
        const int c = idx >> 5, kc = idx & 31;
        cpa16(sb + SK_ST + c * 512 + kc * 16, Kg + (size_t)c * HW + kc * 4);
        cpa16(sb + SV_ST + c * 512 + kc * 16, Vg + (size_t)c * HW + kc * 4);
    }
    cpa_commit();
    cpa_wait0();
    __syncthreads();
    conv_K(stK, (__nv_bfloat16*)(smc + BUF0), tid);
    conv_V(stV, (__nv_bfloat16*)(smc + BUF0 + OFF_VHI), tid);
    __syncthreads();

    float oAcc[8][4];
    #pragma unroll
    for (int nt = 0; nt < 8; ++nt)
        #pragma unroll
        for (int i = 0; i < 4; ++i) oAcc[nt][i] = 0.0f;
    float l0sum = 0.0f, l1sum = 0.0f;

    for (int kt = 0; kt < NKT; ++kt) {
        if (kt + 1 < NKT) {
            const int kk1 = (kt + 1) * BK;
            #pragma unroll
            for (int j = 0; j < 4; ++j) {
                const int idx = tid + 512 * j;
                const int c = idx >> 5, kc = idx & 31;
                cpa16(sb + SK_ST + c * 512 + kc * 16,
                      Kg + (size_t)c * HW + kk1 + kc * 4);
                cpa16(sb + SV_ST + c * 512 + kc * 16,
                      Vg + (size_t)c * HW + kk1 + kc * 4);
            }
            cpa_commit();
        }

        const uint32_t bufb = sb + BUF0 + (uint32_t)(kt & 1) * BUF_SZ;
        const uint32_t kaddr = bufb + (uint32_t)khalf * 64u * 144u + laneK;
        const uint32_t vaddr = bufb + OFF_VHI + (uint32_t)khalf * 128u + laneV;

        // ---- GEMM1: S[16q x 64k] = Q.K^T ----
        float sAcc[8][4];
        #pragma unroll
        for (int nt = 0; nt < 8; ++nt)
            #pragma unroll
            for (int i = 0; i < 4; ++i) sAcc[nt][i] = 0.0f;

        #pragma unroll
        for (int s = 0; s < 4; ++s) {
            #pragma unroll
            for (int np = 0; np < 4; ++np) {
                uint32_t ra[4], rb[4];
                ldsm4(kaddr + (2 * np) * 1152u + s * 32u, ra);
                ldsm4(kaddr + (2 * np + 1) * 1152u + s * 32u, rb);
                mma_bf16(sAcc[2 * np],     qa_hi[s], ra);
                mma_bf16(sAcc[2 * np + 1], qa_hi[s], rb);
                mma_bf16(sAcc[2 * np],     qa_hi[s], ra + 2);
                mma_bf16(sAcc[2 * np + 1], qa_hi[s], rb + 2);
                mma_bf16(sAcc[2 * np],     qa_lo[s], ra);
                mma_bf16(sAcc[2 * np + 1], qa_lo[s], rb);
            }
        }

        // ---- softmax + in-place P fragment build ----
        float* flat = &sAcc[0][0];
        float r0 = 0.0f, r1 = 0.0f;
        #pragma unroll
        for (int s = 0; s < 4; ++s) {
            float p[8];
            #pragma unroll
            for (int i = 0; i < 8; ++i) p[i] = __expf(flat[8 * s + i]);
            r0 += (p[0] + p[1]) + (p[4] + p[5]);
            r1 += (p[2] + p[3]) + (p[6] + p[7]);
            uint32_t h01, l01, h23, l23, h45, l45, h67, l67;
            split_pack(p[0], p[1], h01, l01);
            split_pack(p[2], p[3], h23, l23);
            split_pack(p[4], p[5], h45, l45);
            split_pack(p[6], p[7], h67, l67);
            flat[8 * s + 0] = __uint_as_float(h01);
            flat[8 * s + 1] = __uint_as_float(h23);
            flat[8 * s + 2] = __uint_as_float(h45);
            flat[8 * s + 3] = __uint_as_float(h67);
            flat[8 * s + 4] = __uint_as_float(l01);
            flat[8 * s + 5] = __uint_as_float(l23);
            flat[8 * s + 6] = __uint_as_float(l45);
            flat[8 * s + 7] = __uint_as_float(l67);
        }
        r0 += __shfl_xor_sync(0xffffffffu, r0, 1);
        r0 += __shfl_xor_sync(0xffffffffu, r0, 2);
        r1 += __shfl_xor_sync(0xffffffffu, r1, 1);
        r1 += __shfl_xor_sync(0xffffffffu, r1, 2);
        l0sum += r0;
        l1sum += r1;

        // ---- GEMM2: O[16q x 64c] += P.V^T (partial over this key half) ----
        #pragma unroll
        for (int s = 0; s < 4; ++s) {
            uint32_t ah[4], al[4];
            #pragma unroll
            for (int i = 0; i < 4; ++i) {
                ah[i] = __float_as_uint(flat[8 * s + i]);
                al[i] = __float_as_uint(flat[8 * s + 4 + i]);
            }
            #pragma unroll
            for (int np = 0; np < 4; ++np) {
                uint32_t ra[4], rb[4];
                ldsm4(vaddr + (2 * np) * 2176u + s * 32u, ra);
                ldsm4(vaddr + (2 * np + 1) * 2176u + s * 32u, rb);
                mma_bf16(oAcc[2 * np],     ah, ra);
                mma_bf16(oAcc[2 * np + 1], ah, rb);
                mma_bf16(oAcc[2 * np],     ah, ra + 2);
                mma_bf16(oAcc[2 * np + 1], ah, rb + 2);
                mma_bf16(oAcc[2 * np],     al, ra);
                mma_bf16(oAcc[2 * np + 1], al, rb);
            }
        }

        // ---- convert staged tile kt+1 into the other buffer ----
        if (kt + 1 < NKT) {
            cpa_wait0();
            __syncthreads();
            char* dst = smc + BUF0 + ((kt + 1) & 1) * BUF_SZ;
            conv_K(stK, (__nv_bfloat16*)(dst), tid);
            conv_V(stV, (__nv_bfloat16*)(dst + OFF_VHI), tid);
        }
        __syncthreads();
    }

    // ---- epilogue: pair-reduce partial O and l via stage SMEM, store ----
    __syncthreads();
    float* redO = (float*)smc;             // 8 warps * 32 lanes * 32 floats = 32KB
    float* redL = (float*)(smc + 32768);   // 8 * 32 * 2 floats
    if (khalf == 1) {
        float* dst = redO + (qblk * 32 + lane) * 32;
        #pragma unroll
        for (int nt = 0; nt < 8; ++nt)
            #pragma unroll
            for (int i = 0; i < 4; ++i) dst[nt * 4 + i] = oAcc[nt][i];
        redL[(qblk * 32 + lane) * 2 + 0] = l0sum;
        redL[(qblk * 32 + lane) * 2 + 1] = l1sum;
    }
    __syncthreads();
    if (khalf == 0) {
        const float* src = redO + (qblk * 32 + lane) * 32;
        const float L0 = l0sum + redL[(qblk * 32 + lane) * 2 + 0];
        const float L1 = l1sum + redL[(qblk * 32 + lane) * 2 + 1];
        const float inv0 = 1.0f / L0;
        const float inv1 = 1.0f / L1;
        const int qa = q0 + qblk * 16 + g;
        const int qb = qa + 8;
        #pragma unroll
        for (int nt = 0; nt < 8; ++nt) {
            const int c = nt * 8 + 2 * t;
            outg[(size_t)(64 + c) * HW + qa] = (oAcc[nt][0] + src[nt * 4 + 0]) * inv0;
            outg[(size_t)(65 + c) * HW + qa] = (oAcc[nt][1] + src[nt * 4 + 1]) * inv0;
            outg[(size_t)(64 + c) * HW + qb] = (oAcc[nt][2] + src[nt * 4 + 2]) * inv1;
            outg[(size_t)(65 + c) * HW + qb] = (oAcc[nt][3] + src[nt * 4 + 3]) * inv1;
        }
    }
}

extern "C" void kernel_launch(void* const* d_in, const int* in_sizes, int n_in,
                              void* d_out, int out_size)
{
    const float* content   = (const float*)d_in[0];
    const float* content_s = (const float*)d_in[1];
    const float* style     = (const float*)d_in[2];
    float* out = (float*)d_out;

    cudaFuncSetAttribute(sanet_hmma, cudaFuncAttributeMaxDynamicSharedMemorySize,
                         SMEM_BYTES);
    dim3 grid(HW / BQ, 4);   // 128 CTAs
    sanet_hmma<<<grid, NT, SMEM_BYTES>>>(content, content_s, style, out);
}